// round 6
// baseline (speedup 1.0000x reference)
#include <cuda_runtime.h>
#include <math.h>

// Shapes fixed by the problem:
//   hidden_states (8, 4096, 1024) f32, W (1024,1024) f32, b (1024) f32,
//   alpha (1) f32.  Output (8, 1, 1024) f32.
#define BATCH 8
#define SEQ   4096
#define HID   1024
#define NTHREADS 256              // 8 warps; warp w owns chunk w (128 elems)
#define NBLOCKS  HID              // one block per W row

// Bit layout (identical for x and W — consistency is all that matters):
//   chunk c (= warp), word k (0..3), bit `lane`  <->  element h = c*128 + 4*lane + k

// Scratch (__device__ globals; allocation-free rule). Rewritten every call.
__device__ int      g_dot[HID * BATCH];    // [o][b] exact integer sign-dot
__device__ float    g_wpart[HID];          // per-row sum |W[o,:]|
__device__ unsigned g_ticket = 0;          // last-block-done counter (self-resetting)

__global__ void __launch_bounds__(NTHREADS)
fused_pooler_kernel(const float* __restrict__ x,
                    const float* __restrict__ Wm,
                    const float* __restrict__ bias,
                    const float* __restrict__ alpha,
                    float* __restrict__ out)
{
    const int tid  = threadIdx.x;
    const int warp = tid >> 5;           // chunk index 0..7
    const int lane = tid & 31;
    const int row  = blockIdx.x;
    const int mybatch = lane & 7;        // batch-in-lane

    // ---- Issue ALL 9 independent 16B loads up front (max MLP) ----
    const float4* wr = (const float4*)(Wm + (size_t)row * HID);
    const float4 wv = __ldg(wr + warp * 32 + lane);

    float4 xv[BATCH];
    #pragma unroll
    for (int b = 0; b < BATCH; ++b)
        xv[b] = __ldg((const float4*)(x + (size_t)b * SEQ * HID)
                      + warp * 32 + lane);     // L2-resident after wave 1

    // ---- Pack x sign/nonzero bits; lane keeps only its own batch's 4 words ----
    unsigned xneg[4], xnz[4];
    #pragma unroll
    for (int b = 0; b < BATCH; ++b) {
        const float e[4] = {xv[b].x, xv[b].y, xv[b].z, xv[b].w};
        #pragma unroll
        for (int k = 0; k < 4; ++k) {
            unsigned neg = __ballot_sync(0xffffffffu, e[k] < 0.0f);
            unsigned nz  = __ballot_sync(0xffffffffu, e[k] != 0.0f);
            if (mybatch == b) { xneg[k] = neg; xnz[k] = nz; }
        }
    }

    // ---- W ballots + exact popcount dot for my batch ----
    float asum = fabsf(wv.x) + fabsf(wv.y) + fabsf(wv.z) + fabsf(wv.w);
    int acc = 0;
    {
        const float we[4] = {wv.x, wv.y, wv.z, wv.w};
        #pragma unroll
        for (int k = 0; k < 4; ++k) {
            unsigned wneg = __ballot_sync(0xffffffffu, we[k] < 0.0f);
            unsigned wnz  = __ballot_sync(0xffffffffu, we[k] != 0.0f);
            unsigned valid = xnz[k] & wnz;
            unsigned diff  = (xneg[k] ^ wneg) & valid;
            acc += __popc(valid) - 2 * __popc(diff);
        }
    }

    // asum: warp reduce
    #pragma unroll
    for (int off = 16; off > 0; off >>= 1)
        asum += __shfl_xor_sync(0xffffffffu, asum, off);

    // ---- Block reduction across the 8 chunk-warps ----
    __shared__ int   s_acc[8][BATCH];   // [warp][batch]
    __shared__ float s_asum[8];
    if (lane < BATCH) s_acc[warp][lane] = acc;   // lanes 0-7 carry batches 0-7
    if (lane == 0)    s_asum[warp] = asum;
    __syncthreads();

    if (tid < BATCH) {
        int tot = 0;
        #pragma unroll
        for (int w2 = 0; w2 < 8; ++w2) tot += s_acc[w2][tid];
        g_dot[row * BATCH + tid] = tot;
    }
    if (tid == BATCH) {
        float t = 0.0f;
        #pragma unroll
        for (int w2 = 0; w2 < 8; ++w2) t += s_asum[w2];
        g_wpart[row] = t;
    }

    // ---- Last block does the epilogue ----
    __threadfence();
    __syncthreads();

    __shared__ bool s_last;
    if (tid == 0) {
        unsigned t = atomicAdd(&g_ticket, 1u);
        s_last = (t == (unsigned)(gridDim.x - 1));
        if (s_last) g_ticket = 0;        // reset for next graph replay
    }
    __syncthreads();
    if (!s_last) return;
    __threadfence();                     // acquire: all g_dot/g_wpart visible

    // Reduce sum|W| over 1024 rows with 256 threads
    __shared__ float red[NTHREADS];
    float s = 0.0f;
    #pragma unroll
    for (int k = 0; k < HID / NTHREADS; ++k)
        s += g_wpart[tid + k * NTHREADS];
    red[tid] = s;
    __syncthreads();
    #pragma unroll
    for (int stp = NTHREADS / 2; stp > 0; stp >>= 1) {
        if (tid < stp) red[tid] += red[tid + stp];
        __syncthreads();
    }

    const float wscale = red[0] * (1.0f / ((float)HID * (float)HID));
    const float a      = fmaxf(__ldg(alpha), 1e-5f);
    const float scale  = a * wscale;

    // out[b*HID + o] = tanh(scale * dot[o][b] + bias[o]); idx == b*HID+o
    #pragma unroll
    for (int k = 0; k < (BATCH * HID) / NTHREADS; ++k) {
        int idx = tid + k * NTHREADS;
        int b   = idx >> 10;             // idx / HID
        int o   = idx & (HID - 1);       // idx % HID
        out[idx] = tanhf(scale * (float)g_dot[o * BATCH + b] + __ldg(bias + o));
    }
}

extern "C" void kernel_launch(void* const* d_in, const int* in_sizes, int n_in,
                              void* d_out, int out_size)
{
    const float* x     = (const float*)d_in[0];
    const float* Wm    = (const float*)d_in[1];
    const float* bias  = (const float*)d_in[2];
    const float* alpha = (const float*)d_in[3];
    float* out = (float*)d_out;

    fused_pooler_kernel<<<NBLOCKS, NTHREADS>>>(x, Wm, bias, alpha, out);
}

// round 7
// speedup vs baseline: 1.0045x; 1.0045x over previous
#include <cuda_runtime.h>
#include <math.h>

// Shapes fixed by the problem:
//   hidden_states (8, 4096, 1024) f32, W (1024,1024) f32, b (1024) f32,
//   alpha (1) f32.  Output (8, 1, 1024) f32.
#define BATCH 8
#define SEQ   4096
#define HID   1024
#define NTHREADS 256              // 8 warps; warp w owns chunk w (128 elems)
#define NBLOCKS  HID              // one block per W row

// Bit layout (identical for x and W — consistency is all that matters):
//   chunk c, word k (0..3), bit `lane`  <->  element h = c*128 + 4*lane + k

// Scratch (__device__ globals; allocation-free rule). Rewritten every call.
__device__ uint4    g_xneg[BATCH][8];      // [batch][chunk] 4 sign words
__device__ uint4    g_xnz [BATCH][8];      // [batch][chunk] 4 nonzero words
__device__ int      g_dot[HID * BATCH];    // [o][b] exact integer sign-dot
__device__ float    g_wpart[HID];          // per-row sum |W[o,:]|
__device__ unsigned g_ticket = 0;          // last-block-done counter (self-resetting)

// ---------------------------------------------------------------------------
// Kernel 0: pack x sign/nonzero bits. grid=8 (block b packs batch b),
// 256 threads: warp w packs chunk w (one float4 per lane, 8 ballots).
// ---------------------------------------------------------------------------
__global__ void __launch_bounds__(NTHREADS)
pack_x_kernel(const float* __restrict__ x)
{
    const int b    = blockIdx.x;
    const int warp = threadIdx.x >> 5;   // chunk
    const int lane = threadIdx.x & 31;

    float4 v = __ldg((const float4*)(x + (size_t)b * SEQ * HID) + warp * 32 + lane);
    const float e[4] = {v.x, v.y, v.z, v.w};

    unsigned neg[4], nz[4];
    #pragma unroll
    for (int k = 0; k < 4; ++k) {
        neg[k] = __ballot_sync(0xffffffffu, e[k] < 0.0f);
        nz [k] = __ballot_sync(0xffffffffu, e[k] != 0.0f);
    }
    if (lane == 0) {
        g_xneg[b][warp] = make_uint4(neg[0], neg[1], neg[2], neg[3]);
        g_xnz [b][warp] = make_uint4(nz [0], nz [1], nz [2], nz [3]);
    }
}

// ---------------------------------------------------------------------------
// Kernel 1: one block per W row. Warp w handles chunk w: one float4 of W,
// 8 ballots, batch-in-lane popcount dot. Last block runs the epilogue.
// ---------------------------------------------------------------------------
__global__ void __launch_bounds__(NTHREADS)
fused_pooler_kernel(const float* __restrict__ Wm,
                    const float* __restrict__ bias,
                    const float* __restrict__ alpha,
                    float* __restrict__ out)
{
    const int tid  = threadIdx.x;
    const int warp = tid >> 5;           // chunk index 0..7
    const int lane = tid & 31;
    const int row  = blockIdx.x;
    const int mybatch = lane & 7;        // batch-in-lane

    // W load (DRAM) + packed-x load (L2) issued back-to-back
    const float4 wv = __ldg((const float4*)(Wm + (size_t)row * HID) + warp * 32 + lane);
    const uint4 xn = g_xneg[mybatch][warp];
    const uint4 xz = g_xnz [mybatch][warp];

    float asum = fabsf(wv.x) + fabsf(wv.y) + fabsf(wv.z) + fabsf(wv.w);

    const float we[4] = {wv.x, wv.y, wv.z, wv.w};
    const unsigned xnega[4] = {xn.x, xn.y, xn.z, xn.w};
    const unsigned xnza [4] = {xz.x, xz.y, xz.z, xz.w};

    int acc = 0;
    #pragma unroll
    for (int k = 0; k < 4; ++k) {
        unsigned wneg = __ballot_sync(0xffffffffu, we[k] < 0.0f);
        unsigned wnz  = __ballot_sync(0xffffffffu, we[k] != 0.0f);
        unsigned valid = xnza[k] & wnz;
        unsigned diff  = (xnega[k] ^ wneg) & valid;
        acc += __popc(valid) - 2 * __popc(diff);
    }

    // asum: warp reduce
    #pragma unroll
    for (int off = 16; off > 0; off >>= 1)
        asum += __shfl_xor_sync(0xffffffffu, asum, off);

    // ---- Block reduction across the 8 chunk-warps ----
    __shared__ int   s_acc[8][BATCH];   // [warp][batch]
    __shared__ float s_asum[8];
    if (lane < BATCH) s_acc[warp][lane] = acc;   // lanes 0-7 carry batches 0-7
    if (lane == 0)    s_asum[warp] = asum;
    __syncthreads();

    if (tid < BATCH) {
        int tot = 0;
        #pragma unroll
        for (int w2 = 0; w2 < 8; ++w2) tot += s_acc[w2][tid];
        g_dot[row * BATCH + tid] = tot;
    }
    if (tid == BATCH) {
        float t = 0.0f;
        #pragma unroll
        for (int w2 = 0; w2 < 8; ++w2) t += s_asum[w2];
        g_wpart[row] = t;
    }

    // ---- Last block does the epilogue ----
    __threadfence();
    __syncthreads();

    __shared__ bool s_last;
    if (tid == 0) {
        unsigned t = atomicAdd(&g_ticket, 1u);
        s_last = (t == (unsigned)(gridDim.x - 1));
        if (s_last) g_ticket = 0;        // reset for next graph replay
    }
    __syncthreads();
    if (!s_last) return;
    __threadfence();                     // acquire: all g_dot/g_wpart visible

    // Reduce sum|W| over 1024 rows with 256 threads
    __shared__ float red[NTHREADS];
    float s = 0.0f;
    #pragma unroll
    for (int k = 0; k < HID / NTHREADS; ++k)
        s += g_wpart[tid + k * NTHREADS];
    red[tid] = s;
    __syncthreads();
    #pragma unroll
    for (int stp = NTHREADS / 2; stp > 0; stp >>= 1) {
        if (tid < stp) red[tid] += red[tid + stp];
        __syncthreads();
    }

    const float wscale = red[0] * (1.0f / ((float)HID * (float)HID));
    const float a      = fmaxf(__ldg(alpha), 1e-5f);
    const float scale  = a * wscale;

    // out[b*HID + o] = tanh(scale * dot[o][b] + bias[o]); idx == b*HID+o
    #pragma unroll
    for (int k = 0; k < (BATCH * HID) / NTHREADS; ++k) {
        int idx = tid + k * NTHREADS;
        int b   = idx >> 10;             // idx / HID
        int o   = idx & (HID - 1);       // idx % HID
        out[idx] = tanhf(scale * (float)g_dot[o * BATCH + b] + __ldg(bias + o));
    }
}

extern "C" void kernel_launch(void* const* d_in, const int* in_sizes, int n_in,
                              void* d_out, int out_size)
{
    const float* x     = (const float*)d_in[0];
    const float* Wm    = (const float*)d_in[1];
    const float* bias  = (const float*)d_in[2];
    const float* alpha = (const float*)d_in[3];
    float* out = (float*)d_out;

    pack_x_kernel      <<<BATCH,   NTHREADS>>>(x);
    fused_pooler_kernel<<<NBLOCKS, NTHREADS>>>(Wm, bias, alpha, out);
}

// round 9
// speedup vs baseline: 1.3625x; 1.3565x over previous
#include <cuda_runtime.h>
#include <math.h>

// Shapes fixed by the problem:
//   hidden_states (8, 4096, 1024) f32, W (1024,1024) f32, b (1024) f32,
//   alpha (1) f32.  Output (8, 1, 1024) f32.
#define BATCH 8
#define SEQ   4096
#define HID   1024
#define NTHREADS 256              // 8 warps

// Bit layout (identical for x and W — consistency is all that matters):
//   chunk c, word k (0..3), bit `lane`  <->  element h = c*128 + 4*lane + k

// Scratch (__device__ globals; allocation-free rule). Rewritten every call.
__device__ uint4 g_xneg[BATCH][8];        // [batch][chunk] 4 sign words
__device__ uint4 g_xnz [BATCH][8];        // [batch][chunk] 4 nonzero words
__device__ int   g_dotT[BATCH * HID];     // [b][o] transposed for coalesced epilogue
__device__ float g_wpart[HID];            // per-row sum |W[o,:]|

// ---------------------------------------------------------------------------
// K1: pack x sign/nonzero bits. grid=8 (block b packs batch b), 256 threads:
// warp w packs chunk w (one float4 per lane, 8 ballots).
// ---------------------------------------------------------------------------
__global__ void __launch_bounds__(NTHREADS)
pack_x_kernel(const float* __restrict__ x)
{
    const int b    = blockIdx.x;
    const int warp = threadIdx.x >> 5;   // chunk
    const int lane = threadIdx.x & 31;

    float4 v = __ldg((const float4*)(x + (size_t)b * SEQ * HID) + warp * 32 + lane);
    const float e[4] = {v.x, v.y, v.z, v.w};

    unsigned neg[4], nz[4];
    #pragma unroll
    for (int k = 0; k < 4; ++k) {
        neg[k] = __ballot_sync(0xffffffffu, e[k] < 0.0f);
        nz [k] = __ballot_sync(0xffffffffu, e[k] != 0.0f);
    }
    if (lane == 0) {
        g_xneg[b][warp] = make_uint4(neg[0], neg[1], neg[2], neg[3]);
        g_xnz [b][warp] = make_uint4(nz [0], nz [1], nz [2], nz [3]);
    }
}

// ---------------------------------------------------------------------------
// K2: one block per W row; warp w = chunk w (one float4 of W per thread),
// batch-in-lane popcount dot. Plain stores only — no fence, no atomics.
// ---------------------------------------------------------------------------
__global__ void __launch_bounds__(NTHREADS)
row_kernel(const float* __restrict__ Wm)
{
    const int tid  = threadIdx.x;
    const int warp = tid >> 5;           // chunk
    const int lane = tid & 31;
    const int row  = blockIdx.x;
    const int mybatch = lane & 7;        // batch-in-lane

    const float4 wv = __ldg((const float4*)(Wm + (size_t)row * HID) + warp * 32 + lane);
    const uint4 xn = g_xneg[mybatch][warp];
    const uint4 xz = g_xnz [mybatch][warp];

    float asum = fabsf(wv.x) + fabsf(wv.y) + fabsf(wv.z) + fabsf(wv.w);

    const float we[4] = {wv.x, wv.y, wv.z, wv.w};
    const unsigned xnega[4] = {xn.x, xn.y, xn.z, xn.w};
    const unsigned xnza [4] = {xz.x, xz.y, xz.z, xz.w};

    int acc = 0;
    #pragma unroll
    for (int k = 0; k < 4; ++k) {
        unsigned wneg = __ballot_sync(0xffffffffu, we[k] < 0.0f);
        unsigned wnz  = __ballot_sync(0xffffffffu, we[k] != 0.0f);
        unsigned valid = xnza[k] & wnz;
        unsigned diff  = (xnega[k] ^ wneg) & valid;
        acc += __popc(valid) - 2 * __popc(diff);
    }

    #pragma unroll
    for (int off = 16; off > 0; off >>= 1)
        asum += __shfl_xor_sync(0xffffffffu, asum, off);

    __shared__ int   s_acc[8][BATCH];    // [warp][batch]
    __shared__ float s_asum[8];
    if (lane < BATCH) s_acc[warp][lane] = acc;    // lanes 0-7 carry batches 0-7
    if (lane == 0)    s_asum[warp] = asum;
    __syncthreads();

    if (tid < BATCH) {
        int tot = 0;
        #pragma unroll
        for (int w2 = 0; w2 < 8; ++w2) tot += s_acc[w2][tid];
        g_dotT[tid * HID + row] = tot;            // transposed store
    }
    if (tid == BATCH) {
        float t = 0.0f;
        #pragma unroll
        for (int w2 = 0; w2 < 8; ++w2) t += s_asum[w2];
        g_wpart[row] = t;
    }
}

// ---------------------------------------------------------------------------
// K3: epilogue. grid=8 (block b = batch b), 1024 threads (thread o = column).
// Each block redundantly reduces g_wpart (4 KB, L2-hot) then writes its
// coalesced 1024-float output slice.
// ---------------------------------------------------------------------------
__global__ void __launch_bounds__(1024)
epilogue_kernel(const float* __restrict__ bias,
                const float* __restrict__ alpha,
                float* __restrict__ out)
{
    const int b = blockIdx.x;
    const int o = threadIdx.x;
    const int lane = o & 31;
    const int warp = o >> 5;

    // issue dependent loads early
    const int   dot = g_dotT[b * HID + o];
    const float bo  = __ldg(bias + o);

    // block reduction of g_wpart[1024]: warp shuffle + smem
    float s = g_wpart[o];
    #pragma unroll
    for (int off = 16; off > 0; off >>= 1)
        s += __shfl_xor_sync(0xffffffffu, s, off);

    __shared__ float red[32];
    if (lane == 0) red[warp] = s;
    __syncthreads();
    if (warp == 0) {
        float t = red[lane];
        #pragma unroll
        for (int off = 16; off > 0; off >>= 1)
            t += __shfl_xor_sync(0xffffffffu, t, off);
        if (lane == 0) red[0] = t;
    }
    __syncthreads();

    const float wscale = red[0] * (1.0f / ((float)HID * (float)HID));
    const float a      = fmaxf(__ldg(alpha), 1e-5f);
    const float scale  = a * wscale;

    out[b * HID + o] = tanhf(scale * (float)dot + bo);
}

extern "C" void kernel_launch(void* const* d_in, const int* in_sizes, int n_in,
                              void* d_out, int out_size)
{
    const float* x     = (const float*)d_in[0];
    const float* Wm    = (const float*)d_in[1];
    const float* bias  = (const float*)d_in[2];
    const float* alpha = (const float*)d_in[3];
    float* out = (float*)d_out;

    pack_x_kernel  <<<BATCH, NTHREADS>>>(x);
    row_kernel     <<<HID,   NTHREADS>>>(Wm);
    epilogue_kernel<<<BATCH, 1024>>>(bias, alpha, out);
}